// round 10
// baseline (speedup 1.0000x reference)
#include <cuda_runtime.h>
#include <math.h>

#define NMAX 50000
#define EMAX 1600000
#define HID  128
#define INC  16

// Scratch (allocation-free rule: __device__ globals)
__device__ __align__(16) float g_h [NMAX * HID];   // dinv-scaled pre-agg features
__device__ __align__(16) float g_x1[NMAX * HID];   // conv1 output (post relu)
__device__ __align__(16) float g_x2[NMAX * HID];   // conv2 output (post relu)
__device__ float g_dinv[NMAX];         // deg^-1/2 (incl. self loop)
__device__ int   g_deg [NMAX];         // in-degree (excl. self loop)
__device__ int   g_rowptr[NMAX];       // CSR start offsets
__device__ int   g_cursor[NMAX];       // fill cursors
__device__ int   g_eidx[EMAX];         // CSR: source node per incoming edge
__device__ int   g_row [EMAX];         // normalized edge sources (int32)
__device__ int   g_col [EMAX];         // normalized edge targets (int32)
__device__ int   g_is64;               // dtype flag: 1 if edge_index is int64

// ---------------------------------------------------------------------------
// Detect edge_index dtype: int64 values < 2^31 have every odd 32-bit word == 0.
__global__ void k_dtype(const int* __restrict__ w, int nwords) {
    if (threadIdx.x == 0 && blockIdx.x == 0) {
        int lim = nwords < 256 ? nwords : 256;
        int all0 = 1;
        for (int i = 1; i < lim; i += 2)
            if (w[i] != 0) { all0 = 0; break; }
        g_is64 = all0;
    }
}

__global__ void k_zero(int n) {
    int i = blockIdx.x * blockDim.x + threadIdx.x;
    if (i < n) { g_deg[i] = 0; g_cursor[i] = 0; }
}

// Normalize edge indices to int32 (clamped) AND count in-degree in one pass.
__global__ void k_convert_count(const void* __restrict__ ei, int E, int n) {
    int e = blockIdx.x * blockDim.x + threadIdx.x;
    if (e >= E) return;
    int r, c;
    if (g_is64) {
        const long long* p = (const long long*)ei;
        r = (int)p[e];
        c = (int)p[(size_t)E + e];
    } else {
        const int* p = (const int*)ei;
        r = p[e];
        c = p[E + e];
    }
    if (r < 0) r = 0; if (r >= n) r = n - 1;
    if (c < 0) c = 0; if (c >= n) c = n - 1;
    g_row[e] = r;
    g_col[e] = c;
    atomicAdd(&g_deg[c], 1);
}

// exclusive scan of g_deg -> g_rowptr (+ fused dinv); single block, 1024 threads
__global__ void k_scan(int n) {
    __shared__ int part[1024];
    int tid   = threadIdx.x;
    int chunk = (n + 1023) / 1024;
    int start = tid * chunk;
    int end   = start + chunk; if (end > n) end = n;
    int s = 0;
    for (int i = start; i < end; i++) s += g_deg[i];
    part[tid] = s;
    __syncthreads();
    for (int off = 1; off < 1024; off <<= 1) {
        int v = (tid >= off) ? part[tid - off] : 0;
        __syncthreads();
        part[tid] += v;
        __syncthreads();
    }
    int base = (tid == 0) ? 0 : part[tid - 1];
    for (int i = start; i < end; i++) {
        int d = g_deg[i];
        g_rowptr[i] = base;
        base += d;
        g_dinv[i] = rsqrtf((float)d + 1.0f);   // +1: self loop
    }
}

__global__ void k_fill(int E) {
    int e = blockIdx.x * blockDim.x + threadIdx.x;
    if (e >= E) return;
    int c = g_col[e];
    int pos = g_rowptr[c] + atomicAdd(&g_cursor[c], 1);
    g_eidx[pos] = g_row[e];
}

// h = (x @ conv1_w) * dinv[node]   (N x 16) @ (16 x 128); 16 nodes/block
__global__ void k_gemm1(const float* __restrict__ x, const float* __restrict__ w, int n) {
    __shared__ float xs[16 * INC];
    int base = blockIdx.x * 16;
    int tid  = threadIdx.x;
    for (int i = tid; i < 16 * INC; i += 128) {
        int node = base + i / INC;
        xs[i] = (node < n) ? x[node * INC + (i % INC)] : 0.f;
    }
    __syncthreads();
    float acc[16];
#pragma unroll
    for (int j = 0; j < 16; j++) acc[j] = 0.f;
#pragma unroll
    for (int k = 0; k < INC; k++) {
        float wv = w[k * HID + tid];
#pragma unroll
        for (int j = 0; j < 16; j++) acc[j] += xs[j * INC + k] * wv;
    }
    for (int j = 0; j < 16; j++) {
        int node = base + j;
        if (node < n) g_h[(size_t)node * HID + tid] = acc[j] * g_dinv[node];
    }
}

// h = (g_x1 @ conv2_w) * dinv   (N x 128) @ (128 x 128); 32 nodes/block, 128 thr
__global__ void __launch_bounds__(128) k_gemm2(const float* __restrict__ w, int n) {
    __shared__ float xs[32 * HID];
    int base = blockIdx.x * 32;
    int tid  = threadIdx.x;
    // load 32 node rows (zero-padded at the tail)
    for (int i = tid; i < 32 * HID / 4; i += 128) {
        int node = base + (i * 4) / HID;
        float4 v = (node < n)
            ? reinterpret_cast<const float4*>(g_x1)[((size_t)base * HID) / 4 + i]
            : make_float4(0.f, 0.f, 0.f, 0.f);
        reinterpret_cast<float4*>(xs)[i] = v;
    }
    __syncthreads();
    float acc[32];
#pragma unroll
    for (int j = 0; j < 32; j++) acc[j] = 0.f;
    for (int k = 0; k < HID; k++) {
        float wv = w[k * HID + tid];
#pragma unroll
        for (int j = 0; j < 32; j++) acc[j] += xs[j * HID + k] * wv;
    }
    for (int j = 0; j < 32; j++) {
        int node = base + j;
        if (node < n) g_h[(size_t)node * HID + tid] = acc[j] * g_dinv[node];
    }
}

// Aggregation: one warp per node, lane owns a float4 chunk. g_h is pre-scaled
// by dinv[src], so inner loop is pure load+add. out = relu(dc*(sum+self)+b).
// phase 0: -> g_x1 ; phase 1: -> g_x2
__global__ void k_gather(const float* __restrict__ b, int n, int phase) {
    int g    = blockIdx.x * blockDim.x + threadIdx.x;
    int i    = g >> 5;
    int lane = g & 31;
    if (i >= n) return;

    const float* __restrict__ h = g_h;
    float* __restrict__ out = (phase == 0) ? g_x1 : g_x2;

    float dc    = g_dinv[i];
    int   start = g_rowptr[i];
    int   cnt   = g_deg[i];
    const int* __restrict__ ep = g_eidx + start;

    float4 acc = make_float4(0.f, 0.f, 0.f, 0.f);
    int k = 0;
    for (; k + 4 <= cnt; k += 4) {
        int s0 = ep[k], s1 = ep[k + 1], s2 = ep[k + 2], s3 = ep[k + 3];
        float4 v0 = reinterpret_cast<const float4*>(h + (size_t)s0 * HID)[lane];
        float4 v1 = reinterpret_cast<const float4*>(h + (size_t)s1 * HID)[lane];
        float4 v2 = reinterpret_cast<const float4*>(h + (size_t)s2 * HID)[lane];
        float4 v3 = reinterpret_cast<const float4*>(h + (size_t)s3 * HID)[lane];
        acc.x += (v0.x + v1.x) + (v2.x + v3.x);
        acc.y += (v0.y + v1.y) + (v2.y + v3.y);
        acc.z += (v0.z + v1.z) + (v2.z + v3.z);
        acc.w += (v0.w + v1.w) + (v2.w + v3.w);
    }
    for (; k < cnt; k++) {
        int s = ep[k];
        float4 v = reinterpret_cast<const float4*>(h + (size_t)s * HID)[lane];
        acc.x += v.x; acc.y += v.y; acc.z += v.z; acc.w += v.w;
    }

    // self loop (h pre-scaled): + h_scaled[i]; then * dc
    float4 hv = reinterpret_cast<const float4*>(h + (size_t)i * HID)[lane];
    acc.x = (acc.x + hv.x) * dc;
    acc.y = (acc.y + hv.y) * dc;
    acc.z = (acc.z + hv.z) * dc;
    acc.w = (acc.w + hv.w) * dc;

    const float4 bv = reinterpret_cast<const float4*>(b)[lane];
    acc.x = fmaxf(acc.x + bv.x, 0.f);
    acc.y = fmaxf(acc.y + bv.y, 0.f);
    acc.z = fmaxf(acc.z + bv.z, 0.f);
    acc.w = fmaxf(acc.w + bv.w, 0.f);
    reinterpret_cast<float4*>(out + (size_t)i * HID)[lane] = acc;
}

// ---------------------------------------------------------------------------
// Fused MLP heads: gg (x: 16->32->16), a1 (x1: 128->16->16), a2 (x2: 128->16->16),
// fusion (48->64->32->1, sigmoid). One thread per node, weights in shared.
__global__ void k_mlp(const float* __restrict__ x,
                      const float* ln1w, const float* ln1b,
                      const float* ln2w, const float* ln2b,
                      const float* na1w, const float* na1b,
                      const float* na2w, const float* na2b,
                      const float* na3w, const float* na3b,
                      const float* na4w, const float* na4b,
                      const float* f1w,  const float* f1b,
                      const float* f2w,  const float* f2b,
                      const float* f3w,  const float* f3b,
                      float* __restrict__ out, int n) {
    __shared__ float s[10993];
    float* sln1  = s;          float* sln1b = s + 512;
    float* sln2  = s + 544;    float* sln2b = s + 1056;
    float* sna1  = s + 1072;   float* sna1b = s + 3120;
    float* sna2  = s + 3136;   float* sna2b = s + 3392;
    float* sna3  = s + 3408;   float* sna3b = s + 5456;
    float* sna4  = s + 5472;   float* sna4b = s + 5728;
    float* sf1   = s + 5744;   float* sf1b  = s + 8816;
    float* sf2   = s + 8880;   float* sf2b  = s + 10928;
    float* sf3   = s + 10960;  float* sf3b  = s + 10992;

    int tid = threadIdx.x;
    auto cp = [&](float* d, const float* src, int cnt) {
        for (int i = tid; i < cnt; i += blockDim.x) d[i] = src[i];
    };
    cp(sln1, ln1w, 512);  cp(sln1b, ln1b, 32);
    cp(sln2, ln2w, 512);  cp(sln2b, ln2b, 16);
    cp(sna1, na1w, 2048); cp(sna1b, na1b, 16);
    cp(sna2, na2w, 256);  cp(sna2b, na2b, 16);
    cp(sna3, na3w, 2048); cp(sna3b, na3b, 16);
    cp(sna4, na4w, 256);  cp(sna4b, na4b, 16);
    cp(sf1,  f1w, 3072);  cp(sf1b,  f1b, 64);
    cp(sf2,  f2w, 2048);  cp(sf2b,  f2b, 32);
    cp(sf3,  f3w, 32);    cp(sf3b,  f3b, 1);
    __syncthreads();

    int i = blockIdx.x * blockDim.x + tid;
    if (i >= n) return;

    float xf[48];

    // --- gg path ---
    {
        float xin[INC];
#pragma unroll
        for (int k = 0; k < INC; k++) xin[k] = x[(size_t)i * INC + k];
        float h32[32];
#pragma unroll
        for (int j = 0; j < 32; j++) {
            float a = sln1b[j];
#pragma unroll
            for (int k = 0; k < INC; k++) a += xin[k] * sln1[k * 32 + j];
            h32[j] = fmaxf(a, 0.f);
        }
#pragma unroll
        for (int j = 0; j < 16; j++) {
            float a = sln2b[j];
#pragma unroll
            for (int k = 0; k < 32; k++) a += h32[k] * sln2[k * 16 + j];
            xf[j] = fmaxf(a, 0.f);
        }
    }

    // --- a1 path (from x1) ---
    {
        float t[16];
#pragma unroll
        for (int j = 0; j < 16; j++) t[j] = sna1b[j];
        const float* xr = g_x1 + (size_t)i * HID;
        for (int k4 = 0; k4 < HID / 4; k4++) {
            float4 xv = reinterpret_cast<const float4*>(xr)[k4];
#pragma unroll
            for (int j = 0; j < 16; j++) {
                t[j] += xv.x * sna1[(k4 * 4 + 0) * 16 + j]
                      + xv.y * sna1[(k4 * 4 + 1) * 16 + j]
                      + xv.z * sna1[(k4 * 4 + 2) * 16 + j]
                      + xv.w * sna1[(k4 * 4 + 3) * 16 + j];
            }
        }
#pragma unroll
        for (int j = 0; j < 16; j++) t[j] = fmaxf(t[j], 0.f);
#pragma unroll
        for (int j = 0; j < 16; j++) {
            float a = sna2b[j];
#pragma unroll
            for (int k = 0; k < 16; k++) a += t[k] * sna2[k * 16 + j];
            xf[16 + j] = fmaxf(a, 0.f);
        }
    }

    // --- a2 path (from x2) ---
    {
        float t[16];
#pragma unroll
        for (int j = 0; j < 16; j++) t[j] = sna3b[j];
        const float* xr = g_x2 + (size_t)i * HID;
        for (int k4 = 0; k4 < HID / 4; k4++) {
            float4 xv = reinterpret_cast<const float4*>(xr)[k4];
#pragma unroll
            for (int j = 0; j < 16; j++) {
                t[j] += xv.x * sna3[(k4 * 4 + 0) * 16 + j]
                      + xv.y * sna3[(k4 * 4 + 1) * 16 + j]
                      + xv.z * sna3[(k4 * 4 + 2) * 16 + j]
                      + xv.w * sna3[(k4 * 4 + 3) * 16 + j];
            }
        }
#pragma unroll
        for (int j = 0; j < 16; j++) t[j] = fmaxf(t[j], 0.f);
#pragma unroll
        for (int j = 0; j < 16; j++) {
            float a = sna4b[j];
#pragma unroll
            for (int k = 0; k < 16; k++) a += t[k] * sna4[k * 16 + j];
            xf[32 + j] = fmaxf(a, 0.f);
        }
    }

    // --- fusion head ---
    float h64[64];
#pragma unroll
    for (int j = 0; j < 64; j++) {
        float a = sf1b[j];
#pragma unroll
        for (int k = 0; k < 48; k++) a += xf[k] * sf1[k * 64 + j];
        h64[j] = fmaxf(a, 0.f);
    }
    float h32b[32];
#pragma unroll
    for (int j = 0; j < 32; j++) {
        float a = sf2b[j];
#pragma unroll
        for (int k = 0; k < 64; k++) a += h64[k] * sf2[k * 32 + j];
        h32b[j] = fmaxf(a, 0.f);
    }
    float z = sf3b[0];
#pragma unroll
    for (int k = 0; k < 32; k++) z += h32b[k] * sf3[k];
    out[i] = 1.f / (1.f + expf(-z));
}

// ---------------------------------------------------------------------------
extern "C" void kernel_launch(void* const* d_in, const int* in_sizes, int n_in,
                              void* d_out, int out_size) {
    const float* x        = (const float*)d_in[0];
    const void*  ei       = d_in[1];               // int32 OR int64 — detected on device
    const float* conv1_w  = (const float*)d_in[2];
    const float* conv1_b  = (const float*)d_in[3];
    const float* conv2_w  = (const float*)d_in[4];
    const float* conv2_b  = (const float*)d_in[5];
    const float* ln1_w = (const float*)d_in[6];   const float* ln1_b = (const float*)d_in[7];
    const float* ln2_w = (const float*)d_in[8];   const float* ln2_b = (const float*)d_in[9];
    const float* na1_w = (const float*)d_in[10];  const float* na1_b = (const float*)d_in[11];
    const float* na2_w = (const float*)d_in[12];  const float* na2_b = (const float*)d_in[13];
    const float* na3_w = (const float*)d_in[14];  const float* na3_b = (const float*)d_in[15];
    const float* na4_w = (const float*)d_in[16];  const float* na4_b = (const float*)d_in[17];
    const float* f1_w  = (const float*)d_in[18];  const float* f1_b  = (const float*)d_in[19];
    const float* f2_w  = (const float*)d_in[20];  const float* f2_b  = (const float*)d_in[21];
    const float* f3_w  = (const float*)d_in[22];  const float* f3_b  = (const float*)d_in[23];

    int n = in_sizes[0] / INC;
    int E = in_sizes[1] / 2;        // element count is 2E for either dtype
    if (E > EMAX) E = EMAX;
    if (n > NMAX) n = NMAX;

    int eb = (E + 255) / 256;
    int nb = (n + 255) / 256;

    // ---- dtype detect + CSR build (fused) ----
    k_dtype         <<<1, 32>>>((const int*)ei, E * 2);
    k_zero          <<<nb, 256>>>(n);
    k_convert_count <<<eb, 256>>>(ei, E, n);
    k_scan          <<<1, 1024>>>(n);           // rowptr + dinv
    k_fill          <<<eb, 256>>>(E);

    int gather_blocks = (n * 32 + 255) / 256;

    // ---- conv1 ----
    k_gemm1  <<<(n + 15) / 16, 128>>>(x, conv1_w, n);
    k_gather <<<gather_blocks, 256>>>(conv1_b, n, 0);

    // ---- conv2 ----
    k_gemm2  <<<(n + 31) / 32, 128>>>(conv2_w, n);
    k_gather <<<gather_blocks, 256>>>(conv2_b, n, 1);

    // ---- heads + fusion ----
    k_mlp<<<(n + 127) / 128, 128>>>(x,
        ln1_w, ln1_b, ln2_w, ln2_b,
        na1_w, na1_b, na2_w, na2_b,
        na3_w, na3_b, na4_w, na4_b,
        f1_w, f1_b, f2_w, f2_b, f3_w, f3_b,
        (float*)d_out, n);
}

// round 11
// speedup vs baseline: 1.4841x; 1.4841x over previous
#include <cuda_runtime.h>
#include <math.h>

#define NMAX 50000
#define EMAX 1600000
#define HID  128
#define INC  16

// Scratch (allocation-free rule: __device__ globals)
__device__ __align__(16) float g_h [NMAX * HID];   // dinv-scaled pre-agg features
__device__ __align__(16) float g_x1[NMAX * HID];   // conv1 output (post relu)
__device__ __align__(16) float g_x2[NMAX * HID];   // conv2 output (post relu)
__device__ float g_dinv[NMAX];         // deg^-1/2 (incl. self loop)
__device__ int   g_deg [NMAX];         // in-degree (excl. self loop)
__device__ int   g_rowptr[NMAX];       // CSR segment starts (order-free alloc)
__device__ int   g_cursor[NMAX];       // fill cursors
__device__ int   g_eidx[EMAX];         // CSR: source node per incoming edge
__device__ int   g_row [EMAX];         // normalized edge sources (int32)
__device__ int   g_col [EMAX];         // normalized edge targets (int32)
__device__ int   g_is64;               // dtype flag: 1 if edge_index is int64
__device__ int   g_total;              // segment allocation cursor

// ---------------------------------------------------------------------------
// Detect edge_index dtype: int64 values < 2^31 have every odd 32-bit word == 0.
// One warp, parallel loads + ballot (the old 1-thread serial loop idled the GPU).
__global__ void k_dtype(const int* __restrict__ w, int nwords) {
    int lane = threadIdx.x;
    int idx  = 2 * lane + 1;
    int is0  = (idx < nwords) ? (w[idx] == 0) : 1;
    unsigned m = __ballot_sync(0xFFFFFFFFu, is0);
    if (lane == 0) g_is64 = (m == 0xFFFFFFFFu) ? 1 : 0;
}

__global__ void k_zero(int n) {
    int i = blockIdx.x * blockDim.x + threadIdx.x;
    if (i < n) { g_deg[i] = 0; g_cursor[i] = 0; }
    if (i == 0) g_total = 0;
}

// Normalize edge indices to int32 (clamped) AND count in-degree in one pass.
__global__ void k_convert_count(const void* __restrict__ ei, int E, int n) {
    int e = blockIdx.x * blockDim.x + threadIdx.x;
    if (e >= E) return;
    int r, c;
    if (g_is64) {
        const long long* p = (const long long*)ei;
        r = (int)p[e];
        c = (int)p[(size_t)E + e];
    } else {
        const int* p = (const int*)ei;
        r = p[e];
        c = p[E + e];
    }
    if (r < 0) r = 0; if (r >= n) r = n - 1;
    if (c < 0) c = 0; if (c >= n) c = n - 1;
    g_row[e] = r;
    g_col[e] = c;
    atomicAdd(&g_deg[c], 1);
}

// Segment-base allocation via warp-aggregated atomic (replaces the 78us
// single-block prefix scan; gather never needs ordered offsets, just disjoint
// segments). Also computes dinv. Fully parallel.
__global__ void k_alloc(int n) {
    int i    = blockIdx.x * blockDim.x + threadIdx.x;
    int lane = threadIdx.x & 31;
    int d = (i < n) ? g_deg[i] : 0;
    // inclusive warp scan of d
    int s = d;
#pragma unroll
    for (int off = 1; off < 32; off <<= 1) {
        int v = __shfl_up_sync(0xFFFFFFFFu, s, off);
        if (lane >= off) s += v;
    }
    int warp_total = __shfl_sync(0xFFFFFFFFu, s, 31);
    int base = 0;
    if (lane == 31) base = atomicAdd(&g_total, warp_total);
    base = __shfl_sync(0xFFFFFFFFu, base, 31);
    if (i < n) {
        g_rowptr[i] = base + s - d;            // exclusive within warp
        g_dinv[i]   = rsqrtf((float)d + 1.0f); // +1: self loop
    }
}

__global__ void k_fill(int E) {
    int e = blockIdx.x * blockDim.x + threadIdx.x;
    if (e >= E) return;
    int c = g_col[e];
    int pos = g_rowptr[c] + atomicAdd(&g_cursor[c], 1);
    g_eidx[pos] = g_row[e];
}

// h = (x @ conv1_w) * dinv[node]   (N x 16) @ (16 x 128); 16 nodes/block
__global__ void k_gemm1(const float* __restrict__ x, const float* __restrict__ w, int n) {
    __shared__ float xs[16 * INC];
    int base = blockIdx.x * 16;
    int tid  = threadIdx.x;
    for (int i = tid; i < 16 * INC; i += 128) {
        int node = base + i / INC;
        xs[i] = (node < n) ? x[node * INC + (i % INC)] : 0.f;
    }
    __syncthreads();
    float acc[16];
#pragma unroll
    for (int j = 0; j < 16; j++) acc[j] = 0.f;
#pragma unroll
    for (int k = 0; k < INC; k++) {
        float wv = w[k * HID + tid];
#pragma unroll
        for (int j = 0; j < 16; j++) acc[j] += xs[j * INC + k] * wv;
    }
    for (int j = 0; j < 16; j++) {
        int node = base + j;
        if (node < n) g_h[(size_t)node * HID + tid] = acc[j] * g_dinv[node];
    }
}

// h = (g_x1 @ conv2_w) * dinv   (N x 128) @ (128 x 128)
// Register-tiled: 32 nodes/block, 256 threads; thread = 4 nodes x 4 cols.
// Per k-step: 4 broadcast LDS + 1 LDS.128 + 16 FMA  (vs 1 LDS per FMA before).
__global__ void __launch_bounds__(256) k_gemm2(const float* __restrict__ w, int n) {
    __shared__ float xs[32 * HID];     // 16 KB: node tile
    __shared__ float ws[32 * HID];     // 16 KB: 32-k slab of W
    int base = blockIdx.x * 32;
    int tid  = threadIdx.x;
    int tx   = tid & 31;     // col group: cols tx*4 .. tx*4+3
    int ty   = tid >> 5;     // node group: nodes ty*4 .. ty*4+3

    // stage x tile (zero-pad tail)
    for (int i = tid; i < 32 * HID / 4; i += 256) {
        int node = base + i / (HID / 4);
        float4 v = (node < n)
            ? reinterpret_cast<const float4*>(g_x1 + (size_t)node * HID)[i & (HID / 4 - 1)]
            : make_float4(0.f, 0.f, 0.f, 0.f);
        reinterpret_cast<float4*>(xs)[i] = v;
    }

    float4 acc[4];
#pragma unroll
    for (int j = 0; j < 4; j++) acc[j] = make_float4(0.f, 0.f, 0.f, 0.f);

    for (int kc = 0; kc < HID; kc += 32) {
        __syncthreads();
        for (int i = tid; i < 32 * HID / 4; i += 256) {
            reinterpret_cast<float4*>(ws)[i] =
                reinterpret_cast<const float4*>(w + (size_t)kc * HID)[i];
        }
        __syncthreads();
#pragma unroll
        for (int kk = 0; kk < 32; kk++) {
            float4 wv = reinterpret_cast<float4*>(ws + kk * HID)[tx];
#pragma unroll
            for (int j = 0; j < 4; j++) {
                float xv = xs[(ty * 4 + j) * HID + kc + kk];
                acc[j].x += xv * wv.x;
                acc[j].y += xv * wv.y;
                acc[j].z += xv * wv.z;
                acc[j].w += xv * wv.w;
            }
        }
    }

#pragma unroll
    for (int j = 0; j < 4; j++) {
        int node = base + ty * 4 + j;
        if (node < n) {
            float di = g_dinv[node];
            float4 o = make_float4(acc[j].x * di, acc[j].y * di,
                                   acc[j].z * di, acc[j].w * di);
            reinterpret_cast<float4*>(g_h + (size_t)node * HID)[tx] = o;
        }
    }
}

// Aggregation: one warp per node, lane owns a float4 chunk. g_h is pre-scaled
// by dinv[src], so inner loop is pure load+add. out = relu(dc*(sum+self)+b).
// phase 0: -> g_x1 ; phase 1: -> g_x2
__global__ void k_gather(const float* __restrict__ b, int n, int phase) {
    int g    = blockIdx.x * blockDim.x + threadIdx.x;
    int i    = g >> 5;
    int lane = g & 31;
    if (i >= n) return;

    const float* __restrict__ h = g_h;
    float* __restrict__ out = (phase == 0) ? g_x1 : g_x2;

    float dc    = g_dinv[i];
    int   start = g_rowptr[i];
    int   cnt   = g_deg[i];
    const int* __restrict__ ep = g_eidx + start;

    float4 acc = make_float4(0.f, 0.f, 0.f, 0.f);
    int k = 0;
    for (; k + 4 <= cnt; k += 4) {
        int s0 = ep[k], s1 = ep[k + 1], s2 = ep[k + 2], s3 = ep[k + 3];
        float4 v0 = reinterpret_cast<const float4*>(h + (size_t)s0 * HID)[lane];
        float4 v1 = reinterpret_cast<const float4*>(h + (size_t)s1 * HID)[lane];
        float4 v2 = reinterpret_cast<const float4*>(h + (size_t)s2 * HID)[lane];
        float4 v3 = reinterpret_cast<const float4*>(h + (size_t)s3 * HID)[lane];
        acc.x += (v0.x + v1.x) + (v2.x + v3.x);
        acc.y += (v0.y + v1.y) + (v2.y + v3.y);
        acc.z += (v0.z + v1.z) + (v2.z + v3.z);
        acc.w += (v0.w + v1.w) + (v2.w + v3.w);
    }
    for (; k < cnt; k++) {
        int s = ep[k];
        float4 v = reinterpret_cast<const float4*>(h + (size_t)s * HID)[lane];
        acc.x += v.x; acc.y += v.y; acc.z += v.z; acc.w += v.w;
    }

    // self loop (h pre-scaled): + h_scaled[i]; then * dc
    float4 hv = reinterpret_cast<const float4*>(h + (size_t)i * HID)[lane];
    acc.x = (acc.x + hv.x) * dc;
    acc.y = (acc.y + hv.y) * dc;
    acc.z = (acc.z + hv.z) * dc;
    acc.w = (acc.w + hv.w) * dc;

    const float4 bv = reinterpret_cast<const float4*>(b)[lane];
    acc.x = fmaxf(acc.x + bv.x, 0.f);
    acc.y = fmaxf(acc.y + bv.y, 0.f);
    acc.z = fmaxf(acc.z + bv.z, 0.f);
    acc.w = fmaxf(acc.w + bv.w, 0.f);
    reinterpret_cast<float4*>(out + (size_t)i * HID)[lane] = acc;
}

// ---------------------------------------------------------------------------
// Fused MLP heads: gg (x: 16->32->16), a1 (x1: 128->16->16), a2 (x2: 128->16->16),
// fusion (48->64->32->1, sigmoid). One thread per node, weights in shared.
__global__ void k_mlp(const float* __restrict__ x,
                      const float* ln1w, const float* ln1b,
                      const float* ln2w, const float* ln2b,
                      const float* na1w, const float* na1b,
                      const float* na2w, const float* na2b,
                      const float* na3w, const float* na3b,
                      const float* na4w, const float* na4b,
                      const float* f1w,  const float* f1b,
                      const float* f2w,  const float* f2b,
                      const float* f3w,  const float* f3b,
                      float* __restrict__ out, int n) {
    __shared__ float s[10993];
    float* sln1  = s;          float* sln1b = s + 512;
    float* sln2  = s + 544;    float* sln2b = s + 1056;
    float* sna1  = s + 1072;   float* sna1b = s + 3120;
    float* sna2  = s + 3136;   float* sna2b = s + 3392;
    float* sna3  = s + 3408;   float* sna3b = s + 5456;
    float* sna4  = s + 5472;   float* sna4b = s + 5728;
    float* sf1   = s + 5744;   float* sf1b  = s + 8816;
    float* sf2   = s + 8880;   float* sf2b  = s + 10928;
    float* sf3   = s + 10960;  float* sf3b  = s + 10992;

    int tid = threadIdx.x;
    auto cp = [&](float* d, const float* src, int cnt) {
        for (int i = tid; i < cnt; i += blockDim.x) d[i] = src[i];
    };
    cp(sln1, ln1w, 512);  cp(sln1b, ln1b, 32);
    cp(sln2, ln2w, 512);  cp(sln2b, ln2b, 16);
    cp(sna1, na1w, 2048); cp(sna1b, na1b, 16);
    cp(sna2, na2w, 256);  cp(sna2b, na2b, 16);
    cp(sna3, na3w, 2048); cp(sna3b, na3b, 16);
    cp(sna4, na4w, 256);  cp(sna4b, na4b, 16);
    cp(sf1,  f1w, 3072);  cp(sf1b,  f1b, 64);
    cp(sf2,  f2w, 2048);  cp(sf2b,  f2b, 32);
    cp(sf3,  f3w, 32);    cp(sf3b,  f3b, 1);
    __syncthreads();

    int i = blockIdx.x * blockDim.x + tid;
    if (i >= n) return;

    float xf[48];

    // --- gg path ---
    {
        float xin[INC];
#pragma unroll
        for (int k = 0; k < INC; k++) xin[k] = x[(size_t)i * INC + k];
        float h32[32];
#pragma unroll
        for (int j = 0; j < 32; j++) {
            float a = sln1b[j];
#pragma unroll
            for (int k = 0; k < INC; k++) a += xin[k] * sln1[k * 32 + j];
            h32[j] = fmaxf(a, 0.f);
        }
#pragma unroll
        for (int j = 0; j < 16; j++) {
            float a = sln2b[j];
#pragma unroll
            for (int k = 0; k < 32; k++) a += h32[k] * sln2[k * 16 + j];
            xf[j] = fmaxf(a, 0.f);
        }
    }

    // --- a1 path (from x1) ---
    {
        float t[16];
#pragma unroll
        for (int j = 0; j < 16; j++) t[j] = sna1b[j];
        const float* xr = g_x1 + (size_t)i * HID;
        for (int k4 = 0; k4 < HID / 4; k4++) {
            float4 xv = reinterpret_cast<const float4*>(xr)[k4];
#pragma unroll
            for (int j = 0; j < 16; j++) {
                t[j] += xv.x * sna1[(k4 * 4 + 0) * 16 + j]
                      + xv.y * sna1[(k4 * 4 + 1) * 16 + j]
                      + xv.z * sna1[(k4 * 4 + 2) * 16 + j]
                      + xv.w * sna1[(k4 * 4 + 3) * 16 + j];
            }
        }
#pragma unroll
        for (int j = 0; j < 16; j++) t[j] = fmaxf(t[j], 0.f);
#pragma unroll
        for (int j = 0; j < 16; j++) {
            float a = sna2b[j];
#pragma unroll
            for (int k = 0; k < 16; k++) a += t[k] * sna2[k * 16 + j];
            xf[16 + j] = fmaxf(a, 0.f);
        }
    }

    // --- a2 path (from x2) ---
    {
        float t[16];
#pragma unroll
        for (int j = 0; j < 16; j++) t[j] = sna3b[j];
        const float* xr = g_x2 + (size_t)i * HID;
        for (int k4 = 0; k4 < HID / 4; k4++) {
            float4 xv = reinterpret_cast<const float4*>(xr)[k4];
#pragma unroll
            for (int j = 0; j < 16; j++) {
                t[j] += xv.x * sna3[(k4 * 4 + 0) * 16 + j]
                      + xv.y * sna3[(k4 * 4 + 1) * 16 + j]
                      + xv.z * sna3[(k4 * 4 + 2) * 16 + j]
                      + xv.w * sna3[(k4 * 4 + 3) * 16 + j];
            }
        }
#pragma unroll
        for (int j = 0; j < 16; j++) t[j] = fmaxf(t[j], 0.f);
#pragma unroll
        for (int j = 0; j < 16; j++) {
            float a = sna4b[j];
#pragma unroll
            for (int k = 0; k < 16; k++) a += t[k] * sna4[k * 16 + j];
            xf[32 + j] = fmaxf(a, 0.f);
        }
    }

    // --- fusion head ---
    float h64[64];
#pragma unroll
    for (int j = 0; j < 64; j++) {
        float a = sf1b[j];
#pragma unroll
        for (int k = 0; k < 48; k++) a += xf[k] * sf1[k * 64 + j];
        h64[j] = fmaxf(a, 0.f);
    }
    float h32b[32];
#pragma unroll
    for (int j = 0; j < 32; j++) {
        float a = sf2b[j];
#pragma unroll
        for (int k = 0; k < 64; k++) a += h64[k] * sf2[k * 32 + j];
        h32b[j] = fmaxf(a, 0.f);
    }
    float z = sf3b[0];
#pragma unroll
    for (int k = 0; k < 32; k++) z += h32b[k] * sf3[k];
    out[i] = 1.f / (1.f + expf(-z));
}

// ---------------------------------------------------------------------------
extern "C" void kernel_launch(void* const* d_in, const int* in_sizes, int n_in,
                              void* d_out, int out_size) {
    const float* x        = (const float*)d_in[0];
    const void*  ei       = d_in[1];               // int32 OR int64 — detected on device
    const float* conv1_w  = (const float*)d_in[2];
    const float* conv1_b  = (const float*)d_in[3];
    const float* conv2_w  = (const float*)d_in[4];
    const float* conv2_b  = (const float*)d_in[5];
    const float* ln1_w = (const float*)d_in[6];   const float* ln1_b = (const float*)d_in[7];
    const float* ln2_w = (const float*)d_in[8];   const float* ln2_b = (const float*)d_in[9];
    const float* na1_w = (const float*)d_in[10];  const float* na1_b = (const float*)d_in[11];
    const float* na2_w = (const float*)d_in[12];  const float* na2_b = (const float*)d_in[13];
    const float* na3_w = (const float*)d_in[14];  const float* na3_b = (const float*)d_in[15];
    const float* na4_w = (const float*)d_in[16];  const float* na4_b = (const float*)d_in[17];
    const float* f1_w  = (const float*)d_in[18];  const float* f1_b  = (const float*)d_in[19];
    const float* f2_w  = (const float*)d_in[20];  const float* f2_b  = (const float*)d_in[21];
    const float* f3_w  = (const float*)d_in[22];  const float* f3_b  = (const float*)d_in[23];

    int n = in_sizes[0] / INC;
    int E = in_sizes[1] / 2;        // element count is 2E for either dtype
    if (E > EMAX) E = EMAX;
    if (n > NMAX) n = NMAX;

    int eb = (E + 255) / 256;
    int nb = (n + 255) / 256;

    // ---- dtype detect + CSR build ----
    k_dtype         <<<1, 32>>>((const int*)ei, E * 2);
    k_zero          <<<nb, 256>>>(n);
    k_convert_count <<<eb, 256>>>(ei, E, n);
    k_alloc         <<<nb, 256>>>(n);           // segment bases + dinv (parallel)
    k_fill          <<<eb, 256>>>(E);

    int gather_blocks = (n * 32 + 255) / 256;

    // ---- conv1 ----
    k_gemm1  <<<(n + 15) / 16, 128>>>(x, conv1_w, n);
    k_gather <<<gather_blocks, 256>>>(conv1_b, n, 0);

    // ---- conv2 ----
    k_gemm2  <<<(n + 31) / 32, 256>>>(conv2_w, n);
    k_gather <<<gather_blocks, 256>>>(conv2_b, n, 1);

    // ---- heads + fusion ----
    k_mlp<<<(n + 127) / 128, 128>>>(x,
        ln1_w, ln1_b, ln2_w, ln2_b,
        na1_w, na1_b, na2_w, na2_b,
        na3_w, na3_b, na4_w, na4_b,
        f1_w, f1_b, f2_w, f2_b, f3_w, f3_b,
        (float*)d_out, n);
}

// round 12
// speedup vs baseline: 1.6291x; 1.0977x over previous
#include <cuda_runtime.h>
#include <cuda_fp16.h>
#include <math.h>

#define NMAX 50000
#define EMAX 1600000
#define HID  128
#define INC  16

// Scratch (allocation-free rule: __device__ globals)
__device__ __align__(16) __half g_h [NMAX * HID];  // dinv-scaled pre-agg features (fp16)
__device__ __align__(16) float  g_x1[NMAX * HID];  // conv1 output (post relu)
__device__ __align__(16) float  g_x2[NMAX * HID];  // conv2 output (post relu)
__device__ float g_dinv[NMAX];         // deg^-1/2 (incl. self loop)
__device__ int   g_deg [NMAX];         // in-degree (excl. self loop)
__device__ int   g_rowptr[NMAX];       // CSR segment starts (order-free alloc)
__device__ int   g_cursor[NMAX];       // fill cursors
__device__ int   g_eidx[EMAX];         // CSR: source node per incoming edge
__device__ int   g_row [EMAX];         // normalized edge sources (int32)
__device__ int   g_col [EMAX];         // normalized edge targets (int32)
__device__ int   g_is64;               // dtype flag: 1 if edge_index is int64
__device__ int   g_total;              // segment allocation cursor

// ---------------------------------------------------------------------------
// Fused init: zero deg/cursor arrays AND sniff edge dtype (warp 0 of block 0).
// int64 values < 2^31 have every odd 32-bit word == 0.
__global__ void k_init(const int* __restrict__ w, int nwords, int n) {
    int i = blockIdx.x * blockDim.x + threadIdx.x;
    if (i < n) { g_deg[i] = 0; g_cursor[i] = 0; }
    if (i == 0) g_total = 0;
    if (blockIdx.x == 0 && threadIdx.x < 32) {
        int lane = threadIdx.x;
        int idx  = 2 * lane + 1;
        int is0  = (idx < nwords) ? (w[idx] == 0) : 1;
        unsigned m = __ballot_sync(0xFFFFFFFFu, is0);
        if (lane == 0) g_is64 = (m == 0xFFFFFFFFu) ? 1 : 0;
    }
}

// Normalize edge indices to int32 (clamped) AND count in-degree in one pass.
__global__ void k_convert_count(const void* __restrict__ ei, int E, int n) {
    int e = blockIdx.x * blockDim.x + threadIdx.x;
    if (e >= E) return;
    int r, c;
    if (g_is64) {
        const long long* p = (const long long*)ei;
        r = (int)p[e];
        c = (int)p[(size_t)E + e];
    } else {
        const int* p = (const int*)ei;
        r = p[e];
        c = p[E + e];
    }
    if (r < 0) r = 0; if (r >= n) r = n - 1;
    if (c < 0) c = 0; if (c >= n) c = n - 1;
    g_row[e] = r;
    g_col[e] = c;
    atomicAdd(&g_deg[c], 1);
}

// Segment-base allocation via warp-aggregated atomic; also computes dinv.
__global__ void k_alloc(int n) {
    int i    = blockIdx.x * blockDim.x + threadIdx.x;
    int lane = threadIdx.x & 31;
    int d = (i < n) ? g_deg[i] : 0;
    int s = d;
#pragma unroll
    for (int off = 1; off < 32; off <<= 1) {
        int v = __shfl_up_sync(0xFFFFFFFFu, s, off);
        if (lane >= off) s += v;
    }
    int warp_total = __shfl_sync(0xFFFFFFFFu, s, 31);
    int base = 0;
    if (lane == 31) base = atomicAdd(&g_total, warp_total);
    base = __shfl_sync(0xFFFFFFFFu, base, 31);
    if (i < n) {
        g_rowptr[i] = base + s - d;            // exclusive within warp
        g_dinv[i]   = rsqrtf((float)d + 1.0f); // +1: self loop
    }
}

__global__ void k_fill(int E) {
    int e = blockIdx.x * blockDim.x + threadIdx.x;
    if (e >= E) return;
    int c = g_col[e];
    int pos = g_rowptr[c] + atomicAdd(&g_cursor[c], 1);
    g_eidx[pos] = g_row[e];
}

// h = fp16( (x @ conv1_w) * dinv[node] )   (N x 16) @ (16 x 128); 16 nodes/block
__global__ void k_gemm1(const float* __restrict__ x, const float* __restrict__ w, int n) {
    __shared__ float xs[16 * INC];
    int base = blockIdx.x * 16;
    int tid  = threadIdx.x;
    for (int i = tid; i < 16 * INC; i += 128) {
        int node = base + i / INC;
        xs[i] = (node < n) ? x[node * INC + (i % INC)] : 0.f;
    }
    __syncthreads();
    float acc[16];
#pragma unroll
    for (int j = 0; j < 16; j++) acc[j] = 0.f;
#pragma unroll
    for (int k = 0; k < INC; k++) {
        float wv = w[k * HID + tid];
#pragma unroll
        for (int j = 0; j < 16; j++) acc[j] += xs[j * INC + k] * wv;
    }
    for (int j = 0; j < 16; j++) {
        int node = base + j;
        if (node < n)
            g_h[(size_t)node * HID + tid] = __float2half(acc[j] * g_dinv[node]);
    }
}

// h = fp16( (g_x1 @ conv2_w) * dinv )   (N x 128) @ (128 x 128)
// Register-tiled: 32 nodes/block, 256 threads; thread = 4 nodes x 4 cols.
__global__ void __launch_bounds__(256) k_gemm2(const float* __restrict__ w, int n) {
    __shared__ float xs[32 * HID];     // 16 KB: node tile
    __shared__ float ws[32 * HID];     // 16 KB: 32-k slab of W
    int base = blockIdx.x * 32;
    int tid  = threadIdx.x;
    int tx   = tid & 31;     // col group: cols tx*4 .. tx*4+3
    int ty   = tid >> 5;     // node group: nodes ty*4 .. ty*4+3

    // stage x tile (zero-pad tail)
    for (int i = tid; i < 32 * HID / 4; i += 256) {
        int node = base + i / (HID / 4);
        float4 v = (node < n)
            ? reinterpret_cast<const float4*>(g_x1 + (size_t)node * HID)[i & (HID / 4 - 1)]
            : make_float4(0.f, 0.f, 0.f, 0.f);
        reinterpret_cast<float4*>(xs)[i] = v;
    }

    float4 acc[4];
#pragma unroll
    for (int j = 0; j < 4; j++) acc[j] = make_float4(0.f, 0.f, 0.f, 0.f);

    for (int kc = 0; kc < HID; kc += 32) {
        __syncthreads();
        for (int i = tid; i < 32 * HID / 4; i += 256) {
            reinterpret_cast<float4*>(ws)[i] =
                reinterpret_cast<const float4*>(w + (size_t)kc * HID)[i];
        }
        __syncthreads();
#pragma unroll
        for (int kk = 0; kk < 32; kk++) {
            float4 wv = reinterpret_cast<float4*>(ws + kk * HID)[tx];
#pragma unroll
            for (int j = 0; j < 4; j++) {
                float xv = xs[(ty * 4 + j) * HID + kc + kk];
                acc[j].x += xv * wv.x;
                acc[j].y += xv * wv.y;
                acc[j].z += xv * wv.z;
                acc[j].w += xv * wv.w;
            }
        }
    }

#pragma unroll
    for (int j = 0; j < 4; j++) {
        int node = base + ty * 4 + j;
        if (node < n) {
            float di = g_dinv[node];
            __half2 h01 = __floats2half2_rn(acc[j].x * di, acc[j].y * di);
            __half2 h23 = __floats2half2_rn(acc[j].z * di, acc[j].w * di);
            __half2* dst = reinterpret_cast<__half2*>(g_h + (size_t)node * HID);
            dst[tx * 2]     = h01;
            dst[tx * 2 + 1] = h23;
        }
    }
}

// Aggregation: one warp per node, lane owns 4 halves (8B). g_h pre-scaled by
// dinv[src]; inner loop = pure 8B load + fp32 accumulate (half the L2 traffic
// of the fp32 version). out = relu(dc*(sum+self)+b).
// phase 0: -> g_x1 ; phase 1: -> g_x2
__global__ void k_gather(const float* __restrict__ b, int n, int phase) {
    int g    = blockIdx.x * blockDim.x + threadIdx.x;
    int i    = g >> 5;
    int lane = g & 31;
    if (i >= n) return;

    const __half* __restrict__ h = g_h;
    float* __restrict__ out = (phase == 0) ? g_x1 : g_x2;

    float dc    = g_dinv[i];
    int   start = g_rowptr[i];
    int   cnt   = g_deg[i];
    const int* __restrict__ ep = g_eidx + start;

    float4 acc = make_float4(0.f, 0.f, 0.f, 0.f);

    auto accum = [&](int s) {
        uint2 raw = reinterpret_cast<const uint2*>(h + (size_t)s * HID)[lane];
        __half2 p0 = *reinterpret_cast<__half2*>(&raw.x);
        __half2 p1 = *reinterpret_cast<__half2*>(&raw.y);
        float2 f0 = __half22float2(p0);
        float2 f1 = __half22float2(p1);
        acc.x += f0.x; acc.y += f0.y; acc.z += f1.x; acc.w += f1.y;
    };

    int k = 0;
    for (; k + 4 <= cnt; k += 4) {
        int s0 = ep[k], s1 = ep[k + 1], s2 = ep[k + 2], s3 = ep[k + 3];
        accum(s0); accum(s1); accum(s2); accum(s3);
    }
    for (; k < cnt; k++) accum(ep[k]);

    // self loop (h pre-scaled): + h_scaled[i]; then * dc
    accum(i);
    acc.x *= dc; acc.y *= dc; acc.z *= dc; acc.w *= dc;

    const float4 bv = reinterpret_cast<const float4*>(b)[lane];
    acc.x = fmaxf(acc.x + bv.x, 0.f);
    acc.y = fmaxf(acc.y + bv.y, 0.f);
    acc.z = fmaxf(acc.z + bv.z, 0.f);
    acc.w = fmaxf(acc.w + bv.w, 0.f);
    reinterpret_cast<float4*>(out + (size_t)i * HID)[lane] = acc;
}

// ---------------------------------------------------------------------------
// Fused MLP heads: gg (x: 16->32->16), a1 (x1: 128->16->16), a2 (x2: 128->16->16),
// fusion (48->64->32->1, sigmoid). One thread per node, weights in shared.
__global__ void k_mlp(const float* __restrict__ x,
                      const float* ln1w, const float* ln1b,
                      const float* ln2w, const float* ln2b,
                      const float* na1w, const float* na1b,
                      const float* na2w, const float* na2b,
                      const float* na3w, const float* na3b,
                      const float* na4w, const float* na4b,
                      const float* f1w,  const float* f1b,
                      const float* f2w,  const float* f2b,
                      const float* f3w,  const float* f3b,
                      float* __restrict__ out, int n) {
    __shared__ float s[10993];
    float* sln1  = s;          float* sln1b = s + 512;
    float* sln2  = s + 544;    float* sln2b = s + 1056;
    float* sna1  = s + 1072;   float* sna1b = s + 3120;
    float* sna2  = s + 3136;   float* sna2b = s + 3392;
    float* sna3  = s + 3408;   float* sna3b = s + 5456;
    float* sna4  = s + 5472;   float* sna4b = s + 5728;
    float* sf1   = s + 5744;   float* sf1b  = s + 8816;
    float* sf2   = s + 8880;   float* sf2b  = s + 10928;
    float* sf3   = s + 10960;  float* sf3b  = s + 10992;

    int tid = threadIdx.x;
    auto cp = [&](float* d, const float* src, int cnt) {
        for (int i = tid; i < cnt; i += blockDim.x) d[i] = src[i];
    };
    cp(sln1, ln1w, 512);  cp(sln1b, ln1b, 32);
    cp(sln2, ln2w, 512);  cp(sln2b, ln2b, 16);
    cp(sna1, na1w, 2048); cp(sna1b, na1b, 16);
    cp(sna2, na2w, 256);  cp(sna2b, na2b, 16);
    cp(sna3, na3w, 2048); cp(sna3b, na3b, 16);
    cp(sna4, na4w, 256);  cp(sna4b, na4b, 16);
    cp(sf1,  f1w, 3072);  cp(sf1b,  f1b, 64);
    cp(sf2,  f2w, 2048);  cp(sf2b,  f2b, 32);
    cp(sf3,  f3w, 32);    cp(sf3b,  f3b, 1);
    __syncthreads();

    int i = blockIdx.x * blockDim.x + tid;
    if (i >= n) return;

    float xf[48];

    // --- gg path ---
    {
        float xin[INC];
#pragma unroll
        for (int k = 0; k < INC; k++) xin[k] = x[(size_t)i * INC + k];
        float h32[32];
#pragma unroll
        for (int j = 0; j < 32; j++) {
            float a = sln1b[j];
#pragma unroll
            for (int k = 0; k < INC; k++) a += xin[k] * sln1[k * 32 + j];
            h32[j] = fmaxf(a, 0.f);
        }
#pragma unroll
        for (int j = 0; j < 16; j++) {
            float a = sln2b[j];
#pragma unroll
            for (int k = 0; k < 32; k++) a += h32[k] * sln2[k * 16 + j];
            xf[j] = fmaxf(a, 0.f);
        }
    }

    // --- a1 path (from x1) ---
    {
        float t[16];
#pragma unroll
        for (int j = 0; j < 16; j++) t[j] = sna1b[j];
        const float* xr = g_x1 + (size_t)i * HID;
        for (int k4 = 0; k4 < HID / 4; k4++) {
            float4 xv = reinterpret_cast<const float4*>(xr)[k4];
#pragma unroll
            for (int j = 0; j < 16; j++) {
                t[j] += xv.x * sna1[(k4 * 4 + 0) * 16 + j]
                      + xv.y * sna1[(k4 * 4 + 1) * 16 + j]
                      + xv.z * sna1[(k4 * 4 + 2) * 16 + j]
                      + xv.w * sna1[(k4 * 4 + 3) * 16 + j];
            }
        }
#pragma unroll
        for (int j = 0; j < 16; j++) t[j] = fmaxf(t[j], 0.f);
#pragma unroll
        for (int j = 0; j < 16; j++) {
            float a = sna2b[j];
#pragma unroll
            for (int k = 0; k < 16; k++) a += t[k] * sna2[k * 16 + j];
            xf[16 + j] = fmaxf(a, 0.f);
        }
    }

    // --- a2 path (from x2) ---
    {
        float t[16];
#pragma unroll
        for (int j = 0; j < 16; j++) t[j] = sna3b[j];
        const float* xr = g_x2 + (size_t)i * HID;
        for (int k4 = 0; k4 < HID / 4; k4++) {
            float4 xv = reinterpret_cast<const float4*>(xr)[k4];
#pragma unroll
            for (int j = 0; j < 16; j++) {
                t[j] += xv.x * sna3[(k4 * 4 + 0) * 16 + j]
                      + xv.y * sna3[(k4 * 4 + 1) * 16 + j]
                      + xv.z * sna3[(k4 * 4 + 2) * 16 + j]
                      + xv.w * sna3[(k4 * 4 + 3) * 16 + j];
            }
        }
#pragma unroll
        for (int j = 0; j < 16; j++) t[j] = fmaxf(t[j], 0.f);
#pragma unroll
        for (int j = 0; j < 16; j++) {
            float a = sna4b[j];
#pragma unroll
            for (int k = 0; k < 16; k++) a += t[k] * sna4[k * 16 + j];
            xf[32 + j] = fmaxf(a, 0.f);
        }
    }

    // --- fusion head ---
    float h64[64];
#pragma unroll
    for (int j = 0; j < 64; j++) {
        float a = sf1b[j];
#pragma unroll
        for (int k = 0; k < 48; k++) a += xf[k] * sf1[k * 64 + j];
        h64[j] = fmaxf(a, 0.f);
    }
    float h32b[32];
#pragma unroll
    for (int j = 0; j < 32; j++) {
        float a = sf2b[j];
#pragma unroll
        for (int k = 0; k < 64; k++) a += h64[k] * sf2[k * 32 + j];
        h32b[j] = fmaxf(a, 0.f);
    }
    float z = sf3b[0];
#pragma unroll
    for (int k = 0; k < 32; k++) z += h32b[k] * sf3[k];
    out[i] = 1.f / (1.f + expf(-z));
}

// ---------------------------------------------------------------------------
extern "C" void kernel_launch(void* const* d_in, const int* in_sizes, int n_in,
                              void* d_out, int out_size) {
    const float* x        = (const float*)d_in[0];
    const void*  ei       = d_in[1];               // int32 OR int64 — detected on device
    const float* conv1_w  = (const float*)d_in[2];
    const float* conv1_b  = (const float*)d_in[3];
    const float* conv2_w  = (const float*)d_in[4];
    const float* conv2_b  = (const float*)d_in[5];
    const float* ln1_w = (const float*)d_in[6];   const float* ln1_b = (const float*)d_in[7];
    const float* ln2_w = (const float*)d_in[8];   const float* ln2_b = (const float*)d_in[9];
    const float* na1_w = (const float*)d_in[10];  const float* na1_b = (const float*)d_in[11];
    const float* na2_w = (const float*)d_in[12];  const float* na2_b = (const float*)d_in[13];
    const float* na3_w = (const float*)d_in[14];  const float* na3_b = (const float*)d_in[15];
    const float* na4_w = (const float*)d_in[16];  const float* na4_b = (const float*)d_in[17];
    const float* f1_w  = (const float*)d_in[18];  const float* f1_b  = (const float*)d_in[19];
    const float* f2_w  = (const float*)d_in[20];  const float* f2_b  = (const float*)d_in[21];
    const float* f3_w  = (const float*)d_in[22];  const float* f3_b  = (const float*)d_in[23];

    int n = in_sizes[0] / INC;
    int E = in_sizes[1] / 2;        // element count is 2E for either dtype
    if (E > EMAX) E = EMAX;
    if (n > NMAX) n = NMAX;

    int eb = (E + 255) / 256;
    int nb = (n + 255) / 256;

    // ---- CSR build (init fuses zero + dtype sniff) ----
    k_init          <<<nb, 256>>>((const int*)ei, E * 2, n);
    k_convert_count <<<eb, 256>>>(ei, E, n);
    k_alloc         <<<nb, 256>>>(n);
    k_fill          <<<eb, 256>>>(E);

    int gather_blocks = (n * 32 + 255) / 256;

    // ---- conv1 ----
    k_gemm1  <<<(n + 15) / 16, 128>>>(x, conv1_w, n);
    k_gather <<<gather_blocks, 256>>>(conv1_b, n, 0);

    // ---- conv2 ----
    k_gemm2  <<<(n + 31) / 32, 256>>>(conv2_w, n);
    k_gather <<<gather_blocks, 256>>>(conv2_b, n, 1);

    // ---- heads + fusion ----
    k_mlp<<<(n + 127) / 128, 128>>>(x,
        ln1_w, ln1_b, ln2_w, ln2_b,
        na1_w, na1_b, na2_w, na2_b,
        na3_w, na3_b, na4_w, na4_b,
        f1_w, f1_b, f2_w, f2_b, f3_w, f3_b,
        (float*)d_out, n);
}

// round 13
// speedup vs baseline: 1.7568x; 1.0784x over previous
#include <cuda_runtime.h>
#include <cuda_fp16.h>
#include <mma.h>
#include <math.h>

using namespace nvcuda;

#define NMAX 50000
#define EMAX 1600000
#define HID  128
#define INC  16

// Scratch (allocation-free rule: __device__ globals)
__device__ __align__(16) __half g_h  [NMAX * HID];        // dinv-scaled pre-agg features (fp16)
__device__ __align__(16) __half g_x1h[(NMAX + 64) * HID]; // fp16(x1*dinv), padded tail stays 0
__device__ __align__(16) __half g_w2h[HID * HID];         // conv2_w in fp16
__device__ __align__(16) float  g_x1 [NMAX * HID];        // conv1 output (post relu, fp32)
__device__ __align__(16) float  g_x2 [NMAX * HID];        // conv2 output (post relu, fp32)
__device__ float g_dinv[NMAX];         // deg^-1/2 (incl. self loop)
__device__ int   g_deg [NMAX];         // in-degree (excl. self loop)
__device__ int   g_rowptr[NMAX];       // CSR segment starts (order-free alloc)
__device__ int   g_cursor[NMAX];       // fill cursors
__device__ int   g_eidx[EMAX];         // CSR: source node per incoming edge
__device__ int   g_row [EMAX];         // normalized edge sources (int32)
__device__ int   g_col [EMAX];         // normalized edge targets (int32)
__device__ int   g_is64;               // dtype flag: 1 if edge_index is int64
__device__ int   g_total;              // segment allocation cursor

// ---------------------------------------------------------------------------
// Fused init: zero deg/cursor arrays AND sniff edge dtype (warp 0 of block 0).
__global__ void k_init(const int* __restrict__ w, int nwords, int n) {
    int i = blockIdx.x * blockDim.x + threadIdx.x;
    if (i < n) { g_deg[i] = 0; g_cursor[i] = 0; }
    if (i == 0) g_total = 0;
    if (blockIdx.x == 0 && threadIdx.x < 32) {
        int lane = threadIdx.x;
        int idx  = 2 * lane + 1;
        int is0  = (idx < nwords) ? (w[idx] == 0) : 1;
        unsigned m = __ballot_sync(0xFFFFFFFFu, is0);
        if (lane == 0) g_is64 = (m == 0xFFFFFFFFu) ? 1 : 0;
    }
}

// Normalize edge indices to int32 (clamped) AND count in-degree in one pass.
__global__ void k_convert_count(const void* __restrict__ ei, int E, int n) {
    int e = blockIdx.x * blockDim.x + threadIdx.x;
    if (e >= E) return;
    int r, c;
    if (g_is64) {
        const long long* p = (const long long*)ei;
        r = (int)p[e];
        c = (int)p[(size_t)E + e];
    } else {
        const int* p = (const int*)ei;
        r = p[e];
        c = p[E + e];
    }
    if (r < 0) r = 0; if (r >= n) r = n - 1;
    if (c < 0) c = 0; if (c >= n) c = n - 1;
    g_row[e] = r;
    g_col[e] = c;
    atomicAdd(&g_deg[c], 1);
}

// Segment-base allocation via warp-aggregated atomic; also computes dinv.
__global__ void k_alloc(int n) {
    int i    = blockIdx.x * blockDim.x + threadIdx.x;
    int lane = threadIdx.x & 31;
    int d = (i < n) ? g_deg[i] : 0;
    int s = d;
#pragma unroll
    for (int off = 1; off < 32; off <<= 1) {
        int v = __shfl_up_sync(0xFFFFFFFFu, s, off);
        if (lane >= off) s += v;
    }
    int warp_total = __shfl_sync(0xFFFFFFFFu, s, 31);
    int base = 0;
    if (lane == 31) base = atomicAdd(&g_total, warp_total);
    base = __shfl_sync(0xFFFFFFFFu, base, 31);
    if (i < n) {
        g_rowptr[i] = base + s - d;            // exclusive within warp
        g_dinv[i]   = rsqrtf((float)d + 1.0f); // +1: self loop
    }
}

__global__ void k_fill(int E) {
    int e = blockIdx.x * blockDim.x + threadIdx.x;
    if (e >= E) return;
    int c = g_col[e];
    int pos = g_rowptr[c] + atomicAdd(&g_cursor[c], 1);
    g_eidx[pos] = g_row[e];
}

// conv2_w -> fp16
__global__ void k_w2h(const float* __restrict__ w) {
    int i = blockIdx.x * blockDim.x + threadIdx.x;
    if (i < HID * HID) g_w2h[i] = __float2half(w[i]);
}

// h = fp16( (x @ conv1_w) * dinv[node] )   (N x 16) @ (16 x 128); 16 nodes/block
__global__ void k_gemm1(const float* __restrict__ x, const float* __restrict__ w, int n) {
    __shared__ float xs[16 * INC];
    int base = blockIdx.x * 16;
    int tid  = threadIdx.x;
    for (int i = tid; i < 16 * INC; i += 128) {
        int node = base + i / INC;
        xs[i] = (node < n) ? x[node * INC + (i % INC)] : 0.f;
    }
    __syncthreads();
    float acc[16];
#pragma unroll
    for (int j = 0; j < 16; j++) acc[j] = 0.f;
#pragma unroll
    for (int k = 0; k < INC; k++) {
        float wv = w[k * HID + tid];
#pragma unroll
        for (int j = 0; j < 16; j++) acc[j] += xs[j * INC + k] * wv;
    }
    for (int j = 0; j < 16; j++) {
        int node = base + j;
        if (node < n)
            g_h[(size_t)node * HID + tid] = __float2half(acc[j] * g_dinv[node]);
    }
}

// conv2 GEMM on tensor cores: g_h = fp16( g_x1h @ W2 ), fp32 accumulate.
// g_x1h rows are pre-scaled by dinv, so no epilogue scaling needed.
// Block: 4 warps, 64 rows; warp computes 16 rows x 128 cols via 8x8 HMMA.
__global__ void __launch_bounds__(128) k_gemm2_mma(int n) {
    __shared__ float st[4][16 * HID];   // 32 KB: per-warp fp32 staging
    int warp = threadIdx.x >> 5;
    int lane = threadIdx.x & 31;
    int row0 = blockIdx.x * 64 + warp * 16;
    if (row0 >= n) return;              // warp-uniform exit, no block sync below

    wmma::fragment<wmma::accumulator, 16, 16, 16, float> acc[8];
#pragma unroll
    for (int j = 0; j < 8; j++) wmma::fill_fragment(acc[j], 0.f);

#pragma unroll
    for (int k = 0; k < 8; k++) {
        wmma::fragment<wmma::matrix_a, 16, 16, 16, __half, wmma::row_major> af;
        wmma::load_matrix_sync(af, g_x1h + (size_t)row0 * HID + k * 16, HID);
#pragma unroll
        for (int j = 0; j < 8; j++) {
            wmma::fragment<wmma::matrix_b, 16, 16, 16, __half, wmma::row_major> bf;
            wmma::load_matrix_sync(bf, g_w2h + (size_t)k * 16 * HID + j * 16, HID);
            wmma::mma_sync(acc[j], af, bf, acc[j]);
        }
    }

#pragma unroll
    for (int j = 0; j < 8; j++)
        wmma::store_matrix_sync(&st[warp][j * 16], acc[j], HID, wmma::mem_row_major);
    __syncwarp();

    for (int t = lane; t < 16 * HID / 2; t += 32) {
        int c2  = t * 2;
        int r   = c2 / HID;
        int c   = c2 % HID;
        int row = row0 + r;
        if (row < n) {
            __half2 hv = __floats2half2_rn(st[warp][r * HID + c],
                                           st[warp][r * HID + c + 1]);
            *reinterpret_cast<__half2*>(&g_h[(size_t)row * HID + c]) = hv;
        }
    }
}

// Aggregation: one warp per node, lane owns 4 halves (8B). g_h pre-scaled by
// dinv[src]; inner loop = pure 8B load + fp32 accumulate, 8-way unrolled.
// out = relu(dc*(sum+self)+b).
// phase 0: -> g_x1 (fp32) AND g_x1h = fp16(x1*dc) for the tensor-core gemm2.
// phase 1: -> g_x2
__global__ void k_gather(const float* __restrict__ b, int n, int phase) {
    int g    = blockIdx.x * blockDim.x + threadIdx.x;
    int i    = g >> 5;
    int lane = g & 31;
    if (i >= n) return;

    const __half* __restrict__ h = g_h;

    float dc    = g_dinv[i];
    int   start = g_rowptr[i];
    int   cnt   = g_deg[i];
    const int* __restrict__ ep = g_eidx + start;

    float4 acc = make_float4(0.f, 0.f, 0.f, 0.f);

    auto accum = [&](int s) {
        uint2 raw = reinterpret_cast<const uint2*>(h + (size_t)s * HID)[lane];
        __half2 p0 = *reinterpret_cast<__half2*>(&raw.x);
        __half2 p1 = *reinterpret_cast<__half2*>(&raw.y);
        float2 f0 = __half22float2(p0);
        float2 f1 = __half22float2(p1);
        acc.x += f0.x; acc.y += f0.y; acc.z += f1.x; acc.w += f1.y;
    };

    int k = 0;
    for (; k + 8 <= cnt; k += 8) {
        int s0 = ep[k],     s1 = ep[k + 1], s2 = ep[k + 2], s3 = ep[k + 3];
        int s4 = ep[k + 4], s5 = ep[k + 5], s6 = ep[k + 6], s7 = ep[k + 7];
        accum(s0); accum(s1); accum(s2); accum(s3);
        accum(s4); accum(s5); accum(s6); accum(s7);
    }
    for (; k < cnt; k++) accum(ep[k]);

    // self loop (h pre-scaled): + h_scaled[i]; then * dc
    accum(i);
    acc.x *= dc; acc.y *= dc; acc.z *= dc; acc.w *= dc;

    const float4 bv = reinterpret_cast<const float4*>(b)[lane];
    acc.x = fmaxf(acc.x + bv.x, 0.f);
    acc.y = fmaxf(acc.y + bv.y, 0.f);
    acc.z = fmaxf(acc.z + bv.z, 0.f);
    acc.w = fmaxf(acc.w + bv.w, 0.f);

    if (phase == 0) {
        reinterpret_cast<float4*>(g_x1 + (size_t)i * HID)[lane] = acc;
        __half2 h01 = __floats2half2_rn(acc.x * dc, acc.y * dc);
        __half2 h23 = __floats2half2_rn(acc.z * dc, acc.w * dc);
        __half2* dst = reinterpret_cast<__half2*>(g_x1h + (size_t)i * HID);
        dst[lane * 2]     = h01;
        dst[lane * 2 + 1] = h23;
    } else {
        reinterpret_cast<float4*>(g_x2 + (size_t)i * HID)[lane] = acc;
    }
}

// ---------------------------------------------------------------------------
// Fused MLP heads: gg (x: 16->32->16), a1 (x1: 128->16->16), a2 (x2: 128->16->16),
// fusion (48->64->32->1, sigmoid). One thread per node, weights in shared.
__global__ void k_mlp(const float* __restrict__ x,
                      const float* ln1w, const float* ln1b,
                      const float* ln2w, const float* ln2b,
                      const float* na1w, const float* na1b,
                      const float* na2w, const float* na2b,
                      const float* na3w, const float* na3b,
                      const float* na4w, const float* na4b,
                      const float* f1w,  const float* f1b,
                      const float* f2w,  const float* f2b,
                      const float* f3w,  const float* f3b,
                      float* __restrict__ out, int n) {
    __shared__ float s[10993];
    float* sln1  = s;          float* sln1b = s + 512;
    float* sln2  = s + 544;    float* sln2b = s + 1056;
    float* sna1  = s + 1072;   float* sna1b = s + 3120;
    float* sna2  = s + 3136;   float* sna2b = s + 3392;
    float* sna3  = s + 3408;   float* sna3b = s + 5456;
    float* sna4  = s + 5472;   float* sna4b = s + 5728;
    float* sf1   = s + 5744;   float* sf1b  = s + 8816;
    float* sf2   = s + 8880;   float* sf2b  = s + 10928;
    float* sf3   = s + 10960;  float* sf3b  = s + 10992;

    int tid = threadIdx.x;
    auto cp = [&](float* d, const float* src, int cnt) {
        for (int i = tid; i < cnt; i += blockDim.x) d[i] = src[i];
    };
    cp(sln1, ln1w, 512);  cp(sln1b, ln1b, 32);
    cp(sln2, ln2w, 512);  cp(sln2b, ln2b, 16);
    cp(sna1, na1w, 2048); cp(sna1b, na1b, 16);
    cp(sna2, na2w, 256);  cp(sna2b, na2b, 16);
    cp(sna3, na3w, 2048); cp(sna3b, na3b, 16);
    cp(sna4, na4w, 256);  cp(sna4b, na4b, 16);
    cp(sf1,  f1w, 3072);  cp(sf1b,  f1b, 64);
    cp(sf2,  f2w, 2048);  cp(sf2b,  f2b, 32);
    cp(sf3,  f3w, 32);    cp(sf3b,  f3b, 1);
    __syncthreads();

    int i = blockIdx.x * blockDim.x + tid;
    if (i >= n) return;

    float xf[48];

    // --- gg path ---
    {
        float xin[INC];
#pragma unroll
        for (int k = 0; k < INC; k++) xin[k] = x[(size_t)i * INC + k];
        float h32[32];
#pragma unroll
        for (int j = 0; j < 32; j++) {
            float a = sln1b[j];
#pragma unroll
            for (int k = 0; k < INC; k++) a += xin[k] * sln1[k * 32 + j];
            h32[j] = fmaxf(a, 0.f);
        }
#pragma unroll
        for (int j = 0; j < 16; j++) {
            float a = sln2b[j];
#pragma unroll
            for (int k = 0; k < 32; k++) a += h32[k] * sln2[k * 16 + j];
            xf[j] = fmaxf(a, 0.f);
        }
    }

    // --- a1 path (from x1) ---
    {
        float t[16];
#pragma unroll
        for (int j = 0; j < 16; j++) t[j] = sna1b[j];
        const float* xr = g_x1 + (size_t)i * HID;
        for (int k4 = 0; k4 < HID / 4; k4++) {
            float4 xv = reinterpret_cast<const float4*>(xr)[k4];
#pragma unroll
            for (int j = 0; j < 16; j++) {
                t[j] += xv.x * sna1[(k4 * 4 + 0) * 16 + j]
                      + xv.y * sna1[(k4 * 4 + 1) * 16 + j]
                      + xv.z * sna1[(k4 * 4 + 2) * 16 + j]
                      + xv.w * sna1[(k4 * 4 + 3) * 16 + j];
            }
        }
#pragma unroll
        for (int j = 0; j < 16; j++) t[j] = fmaxf(t[j], 0.f);
#pragma unroll
        for (int j = 0; j < 16; j++) {
            float a = sna2b[j];
#pragma unroll
            for (int k = 0; k < 16; k++) a += t[k] * sna2[k * 16 + j];
            xf[16 + j] = fmaxf(a, 0.f);
        }
    }

    // --- a2 path (from x2) ---
    {
        float t[16];
#pragma unroll
        for (int j = 0; j < 16; j++) t[j] = sna3b[j];
        const float* xr = g_x2 + (size_t)i * HID;
        for (int k4 = 0; k4 < HID / 4; k4++) {
            float4 xv = reinterpret_cast<const float4*>(xr)[k4];
#pragma unroll
            for (int j = 0; j < 16; j++) {
                t[j] += xv.x * sna3[(k4 * 4 + 0) * 16 + j]
                      + xv.y * sna3[(k4 * 4 + 1) * 16 + j]
                      + xv.z * sna3[(k4 * 4 + 2) * 16 + j]
                      + xv.w * sna3[(k4 * 4 + 3) * 16 + j];
            }
        }
#pragma unroll
        for (int j = 0; j < 16; j++) t[j] = fmaxf(t[j], 0.f);
#pragma unroll
        for (int j = 0; j < 16; j++) {
            float a = sna4b[j];
#pragma unroll
            for (int k = 0; k < 16; k++) a += t[k] * sna4[k * 16 + j];
            xf[32 + j] = fmaxf(a, 0.f);
        }
    }

    // --- fusion head ---
    float h64[64];
#pragma unroll
    for (int j = 0; j < 64; j++) {
        float a = sf1b[j];
#pragma unroll
        for (int k = 0; k < 48; k++) a += xf[k] * sf1[k * 64 + j];
        h64[j] = fmaxf(a, 0.f);
    }
    float h32b[32];
#pragma unroll
    for (int j = 0; j < 32; j++) {
        float a = sf2b[j];
#pragma unroll
        for (int k = 0; k < 64; k++) a += h64[k] * sf2[k * 32 + j];
        h32b[j] = fmaxf(a, 0.f);
    }
    float z = sf3b[0];
#pragma unroll
    for (int k = 0; k < 32; k++) z += h32b[k] * sf3[k];
    out[i] = 1.f / (1.f + expf(-z));
}

// ---------------------------------------------------------------------------
extern "C" void kernel_launch(void* const* d_in, const int* in_sizes, int n_in,
                              void* d_out, int out_size) {
    const float* x        = (const float*)d_in[0];
    const void*  ei       = d_in[1];               // int32 OR int64 — detected on device
    const float* conv1_w  = (const float*)d_in[2];
    const float* conv1_b  = (const float*)d_in[3];
    const float* conv2_w  = (const float*)d_in[4];
    const float* conv2_b  = (const float*)d_in[5];
    const float* ln1_w = (const float*)d_in[6];   const float* ln1_b = (const float*)d_in[7];
    const float* ln2_w = (const float*)d_in[8];   const float* ln2_b = (const float*)d_in[9];
    const float* na1_w = (const float*)d_in[10];  const float* na1_b = (const float*)d_in[11];
    const float* na2_w = (const float*)d_in[12];  const float* na2_b = (const float*)d_in[13];
    const float* na3_w = (const float*)d_in[14];  const float* na3_b = (const float*)d_in[15];
    const float* na4_w = (const float*)d_in[16];  const float* na4_b = (const float*)d_in[17];
    const float* f1_w  = (const float*)d_in[18];  const float* f1_b  = (const float*)d_in[19];
    const float* f2_w  = (const float*)d_in[20];  const float* f2_b  = (const float*)d_in[21];
    const float* f3_w  = (const float*)d_in[22];  const float* f3_b  = (const float*)d_in[23];

    int n = in_sizes[0] / INC;
    int E = in_sizes[1] / 2;        // element count is 2E for either dtype
    if (E > EMAX) E = EMAX;
    if (n > NMAX) n = NMAX;

    int eb = (E + 255) / 256;
    int nb = (n + 255) / 256;

    // ---- CSR build ----
    k_init          <<<nb, 256>>>((const int*)ei, E * 2, n);
    k_convert_count <<<eb, 256>>>(ei, E, n);
    k_alloc         <<<nb, 256>>>(n);
    k_fill          <<<eb, 256>>>(E);
    k_w2h           <<<64, 256>>>(conv2_w);

    int gather_blocks = (n * 32 + 255) / 256;

    // ---- conv1 ----
    k_gemm1  <<<(n + 15) / 16, 128>>>(x, conv1_w, n);
    k_gather <<<gather_blocks, 256>>>(conv1_b, n, 0);

    // ---- conv2 (tensor cores) ----
    k_gemm2_mma <<<(n + 63) / 64, 128>>>(n);
    k_gather    <<<gather_blocks, 256>>>(conv2_b, n, 1);

    // ---- heads + fusion ----
    k_mlp<<<(n + 127) / 128, 128>>>(x,
        ln1_w, ln1_b, ln2_w, ln2_b,
        na1_w, na1_b, na2_w, na2_b,
        na3_w, na3_b, na4_w, na4_b,
        f1_w, f1_b, f2_w, f2_b, f3_w, f3_b,
        (float*)d_out, n);
}

// round 14
// speedup vs baseline: 1.8334x; 1.0436x over previous
#include <cuda_runtime.h>
#include <cuda_fp16.h>
#include <mma.h>
#include <math.h>

using namespace nvcuda;

#define NMAX 50000
#define EMAX 1600000
#define HID  128
#define INC  16

// Scratch (allocation-free rule: __device__ globals)
__device__ __align__(16) __half g_h  [NMAX * HID];        // dinv-scaled pre-agg features (fp16)
__device__ __align__(16) __half g_x1h[(NMAX + 64) * HID]; // fp16(x1*dinv); mlp de-scales; pad=0
__device__ __align__(16) __half g_x2h[NMAX * HID];        // fp16(x2) for mlp a2 path
__device__ __align__(16) __half g_w2h[HID * HID];         // conv2_w in fp16
__device__ float g_dinv[NMAX];         // deg^-1/2 (incl. self loop)
__device__ int   g_deg [NMAX];         // in-degree (excl. self loop)
__device__ int   g_rowptr[NMAX];       // CSR segment starts (order-free alloc)
__device__ int   g_cursor[NMAX];       // fill cursors
__device__ int   g_eidx[EMAX];         // CSR: source node per incoming edge
__device__ int   g_is64;               // dtype flag: 1 if edge_index is int64
__device__ int   g_total;              // segment allocation cursor

// ---------------------------------------------------------------------------
// Fused init: zero deg/cursor, sniff edge dtype (warp 0, block 0), convert W2
// to fp16 (first 16384 threads).
__global__ void k_init(const int* __restrict__ w, int nwords, int n,
                       const float* __restrict__ w2) {
    int i = blockIdx.x * blockDim.x + threadIdx.x;
    if (i < n) { g_deg[i] = 0; g_cursor[i] = 0; }
    if (i == 0) g_total = 0;
    if (i < HID * HID) g_w2h[i] = __float2half(w2[i]);
    if (blockIdx.x == 0 && threadIdx.x < 32) {
        int lane = threadIdx.x;
        int idx  = 2 * lane + 1;
        int is0  = (idx < nwords) ? (w[idx] == 0) : 1;
        unsigned m = __ballot_sync(0xFFFFFFFFu, is0);
        if (lane == 0) g_is64 = (m == 0xFFFFFFFFu) ? 1 : 0;
    }
}

// Count in-degree straight from the input edge list (no intermediates).
__global__ void k_count(const void* __restrict__ ei, int E, int n) {
    int e = blockIdx.x * blockDim.x + threadIdx.x;
    if (e >= E) return;
    int c;
    if (g_is64) c = (int)((const long long*)ei)[(size_t)E + e];
    else        c = ((const int*)ei)[E + e];
    if (c < 0) c = 0; if (c >= n) c = n - 1;
    atomicAdd(&g_deg[c], 1);
}

// Segment-base allocation via warp-aggregated atomic; also computes dinv.
__global__ void k_alloc(int n) {
    int i    = blockIdx.x * blockDim.x + threadIdx.x;
    int lane = threadIdx.x & 31;
    int d = (i < n) ? g_deg[i] : 0;
    int s = d;
#pragma unroll
    for (int off = 1; off < 32; off <<= 1) {
        int v = __shfl_up_sync(0xFFFFFFFFu, s, off);
        if (lane >= off) s += v;
    }
    int warp_total = __shfl_sync(0xFFFFFFFFu, s, 31);
    int base = 0;
    if (lane == 31) base = atomicAdd(&g_total, warp_total);
    base = __shfl_sync(0xFFFFFFFFu, base, 31);
    if (i < n) {
        g_rowptr[i] = base + s - d;            // exclusive within warp
        g_dinv[i]   = rsqrtf((float)d + 1.0f); // +1: self loop
    }
}

// Fill CSR, re-deriving (r,c) from the input edge list.
__global__ void k_fill(const void* __restrict__ ei, int E, int n) {
    int e = blockIdx.x * blockDim.x + threadIdx.x;
    if (e >= E) return;
    int r, c;
    if (g_is64) {
        const long long* p = (const long long*)ei;
        r = (int)p[e];
        c = (int)p[(size_t)E + e];
    } else {
        const int* p = (const int*)ei;
        r = p[e];
        c = p[E + e];
    }
    if (r < 0) r = 0; if (r >= n) r = n - 1;
    if (c < 0) c = 0; if (c >= n) c = n - 1;
    int pos = g_rowptr[c] + atomicAdd(&g_cursor[c], 1);
    g_eidx[pos] = r;
}

// h = fp16( (x @ conv1_w) * dinv[node] )   (N x 16) @ (16 x 128); 16 nodes/block
__global__ void k_gemm1(const float* __restrict__ x, const float* __restrict__ w, int n) {
    __shared__ float xs[16 * INC];
    int base = blockIdx.x * 16;
    int tid  = threadIdx.x;
    for (int i = tid; i < 16 * INC; i += 128) {
        int node = base + i / INC;
        xs[i] = (node < n) ? x[node * INC + (i % INC)] : 0.f;
    }
    __syncthreads();
    float acc[16];
#pragma unroll
    for (int j = 0; j < 16; j++) acc[j] = 0.f;
#pragma unroll
    for (int k = 0; k < INC; k++) {
        float wv = w[k * HID + tid];
#pragma unroll
        for (int j = 0; j < 16; j++) acc[j] += xs[j * INC + k] * wv;
    }
    for (int j = 0; j < 16; j++) {
        int node = base + j;
        if (node < n)
            g_h[(size_t)node * HID + tid] = __float2half(acc[j] * g_dinv[node]);
    }
}

// conv2 GEMM on tensor cores: g_h = fp16( g_x1h @ W2 ), fp32 accumulate.
// g_x1h rows pre-scaled by dinv -> no epilogue scaling.
// Block: 4 warps, 64 rows; warp computes 16 rows x 128 cols via 8x8 HMMA.
__global__ void __launch_bounds__(128) k_gemm2_mma(int n) {
    __shared__ float st[4][16 * HID];   // 32 KB: per-warp fp32 staging
    int warp = threadIdx.x >> 5;
    int lane = threadIdx.x & 31;
    int row0 = blockIdx.x * 64 + warp * 16;
    if (row0 >= n) return;              // warp-uniform exit

    wmma::fragment<wmma::accumulator, 16, 16, 16, float> acc[8];
#pragma unroll
    for (int j = 0; j < 8; j++) wmma::fill_fragment(acc[j], 0.f);

#pragma unroll
    for (int k = 0; k < 8; k++) {
        wmma::fragment<wmma::matrix_a, 16, 16, 16, __half, wmma::row_major> af;
        wmma::load_matrix_sync(af, g_x1h + (size_t)row0 * HID + k * 16, HID);
#pragma unroll
        for (int j = 0; j < 8; j++) {
            wmma::fragment<wmma::matrix_b, 16, 16, 16, __half, wmma::row_major> bf;
            wmma::load_matrix_sync(bf, g_w2h + (size_t)k * 16 * HID + j * 16, HID);
            wmma::mma_sync(acc[j], af, bf, acc[j]);
        }
    }

#pragma unroll
    for (int j = 0; j < 8; j++)
        wmma::store_matrix_sync(&st[warp][j * 16], acc[j], HID, wmma::mem_row_major);
    __syncwarp();

    for (int t = lane; t < 16 * HID / 2; t += 32) {
        int c2  = t * 2;
        int r   = c2 / HID;
        int c   = c2 % HID;
        int row = row0 + r;
        if (row < n) {
            __half2 hv = __floats2half2_rn(st[warp][r * HID + c],
                                           st[warp][r * HID + c + 1]);
            *reinterpret_cast<__half2*>(&g_h[(size_t)row * HID + c]) = hv;
        }
    }
}

// Aggregation: one warp per node, lane owns 4 halves (8B); fp32 accumulate,
// 8-way unrolled. out = relu(dc*(sum+self)+b).
// phase 0: write g_x1h = fp16(out*dc) only (gemm2 input; mlp de-scales later).
// phase 1: write g_x2h = fp16(out).
__global__ void k_gather(const float* __restrict__ b, int n, int phase) {
    int g    = blockIdx.x * blockDim.x + threadIdx.x;
    int i    = g >> 5;
    int lane = g & 31;
    if (i >= n) return;

    const __half* __restrict__ h = g_h;

    float dc    = g_dinv[i];
    int   start = g_rowptr[i];
    int   cnt   = g_deg[i];
    const int* __restrict__ ep = g_eidx + start;

    float4 acc = make_float4(0.f, 0.f, 0.f, 0.f);

    auto accum = [&](int s) {
        uint2 raw = reinterpret_cast<const uint2*>(h + (size_t)s * HID)[lane];
        __half2 p0 = *reinterpret_cast<__half2*>(&raw.x);
        __half2 p1 = *reinterpret_cast<__half2*>(&raw.y);
        float2 f0 = __half22float2(p0);
        float2 f1 = __half22float2(p1);
        acc.x += f0.x; acc.y += f0.y; acc.z += f1.x; acc.w += f1.y;
    };

    int k = 0;
    for (; k + 8 <= cnt; k += 8) {
        int s0 = ep[k],     s1 = ep[k + 1], s2 = ep[k + 2], s3 = ep[k + 3];
        int s4 = ep[k + 4], s5 = ep[k + 5], s6 = ep[k + 6], s7 = ep[k + 7];
        accum(s0); accum(s1); accum(s2); accum(s3);
        accum(s4); accum(s5); accum(s6); accum(s7);
    }
    for (; k < cnt; k++) accum(ep[k]);

    // self loop (h pre-scaled): + h_scaled[i]; then * dc
    accum(i);
    acc.x *= dc; acc.y *= dc; acc.z *= dc; acc.w *= dc;

    const float4 bv = reinterpret_cast<const float4*>(b)[lane];
    acc.x = fmaxf(acc.x + bv.x, 0.f);
    acc.y = fmaxf(acc.y + bv.y, 0.f);
    acc.z = fmaxf(acc.z + bv.z, 0.f);
    acc.w = fmaxf(acc.w + bv.w, 0.f);

    if (phase == 0) {
        __half2 h01 = __floats2half2_rn(acc.x * dc, acc.y * dc);
        __half2 h23 = __floats2half2_rn(acc.z * dc, acc.w * dc);
        __half2* dst = reinterpret_cast<__half2*>(g_x1h + (size_t)i * HID);
        dst[lane * 2]     = h01;
        dst[lane * 2 + 1] = h23;
    } else {
        __half2 h01 = __floats2half2_rn(acc.x, acc.y);
        __half2 h23 = __floats2half2_rn(acc.z, acc.w);
        __half2* dst = reinterpret_cast<__half2*>(g_x2h + (size_t)i * HID);
        dst[lane * 2]     = h01;
        dst[lane * 2 + 1] = h23;
    }
}

// ---------------------------------------------------------------------------
// Fused MLP heads. a1 reads g_x1h and de-scales by 1/dinv (x1h = x1*dinv);
// a2 reads g_x2h directly. One thread per node, weights in shared.
__global__ void k_mlp(const float* __restrict__ x,
                      const float* ln1w, const float* ln1b,
                      const float* ln2w, const float* ln2b,
                      const float* na1w, const float* na1b,
                      const float* na2w, const float* na2b,
                      const float* na3w, const float* na3b,
                      const float* na4w, const float* na4b,
                      const float* f1w,  const float* f1b,
                      const float* f2w,  const float* f2b,
                      const float* f3w,  const float* f3b,
                      float* __restrict__ out, int n) {
    __shared__ float s[10993];
    float* sln1  = s;          float* sln1b = s + 512;
    float* sln2  = s + 544;    float* sln2b = s + 1056;
    float* sna1  = s + 1072;   float* sna1b = s + 3120;
    float* sna2  = s + 3136;   float* sna2b = s + 3392;
    float* sna3  = s + 3408;   float* sna3b = s + 5456;
    float* sna4  = s + 5472;   float* sna4b = s + 5728;
    float* sf1   = s + 5744;   float* sf1b  = s + 8816;
    float* sf2   = s + 8880;   float* sf2b  = s + 10928;
    float* sf3   = s + 10960;  float* sf3b  = s + 10992;

    int tid = threadIdx.x;
    auto cp = [&](float* d, const float* src, int cnt) {
        for (int i = tid; i < cnt; i += blockDim.x) d[i] = src[i];
    };
    cp(sln1, ln1w, 512);  cp(sln1b, ln1b, 32);
    cp(sln2, ln2w, 512);  cp(sln2b, ln2b, 16);
    cp(sna1, na1w, 2048); cp(sna1b, na1b, 16);
    cp(sna2, na2w, 256);  cp(sna2b, na2b, 16);
    cp(sna3, na3w, 2048); cp(sna3b, na3b, 16);
    cp(sna4, na4w, 256);  cp(sna4b, na4b, 16);
    cp(sf1,  f1w, 3072);  cp(sf1b,  f1b, 64);
    cp(sf2,  f2w, 2048);  cp(sf2b,  f2b, 32);
    cp(sf3,  f3w, 32);    cp(sf3b,  f3b, 1);
    __syncthreads();

    int i = blockIdx.x * blockDim.x + tid;
    if (i >= n) return;

    float xf[48];

    // --- gg path ---
    {
        float xin[INC];
#pragma unroll
        for (int k = 0; k < INC; k++) xin[k] = x[(size_t)i * INC + k];
        float h32[32];
#pragma unroll
        for (int j = 0; j < 32; j++) {
            float a = sln1b[j];
#pragma unroll
            for (int k = 0; k < INC; k++) a += xin[k] * sln1[k * 32 + j];
            h32[j] = fmaxf(a, 0.f);
        }
#pragma unroll
        for (int j = 0; j < 16; j++) {
            float a = sln2b[j];
#pragma unroll
            for (int k = 0; k < 32; k++) a += h32[k] * sln2[k * 16 + j];
            xf[j] = fmaxf(a, 0.f);
        }
    }

    // --- a1 path (from x1 = g_x1h / dinv) ---
    {
        float rdc = 1.0f / g_dinv[i];
        float t[16];
#pragma unroll
        for (int j = 0; j < 16; j++) t[j] = sna1b[j];
        const __half2* xr = reinterpret_cast<const __half2*>(g_x1h + (size_t)i * HID);
        for (int k2 = 0; k2 < HID / 2; k2++) {
            float2 f = __half22float2(xr[k2]);
            float x0 = f.x * rdc, x1v = f.y * rdc;
#pragma unroll
            for (int j = 0; j < 16; j++)
                t[j] += x0 * sna1[(k2 * 2) * 16 + j] + x1v * sna1[(k2 * 2 + 1) * 16 + j];
        }
#pragma unroll
        for (int j = 0; j < 16; j++) t[j] = fmaxf(t[j], 0.f);
#pragma unroll
        for (int j = 0; j < 16; j++) {
            float a = sna2b[j];
#pragma unroll
            for (int k = 0; k < 16; k++) a += t[k] * sna2[k * 16 + j];
            xf[16 + j] = fmaxf(a, 0.f);
        }
    }

    // --- a2 path (from g_x2h) ---
    {
        float t[16];
#pragma unroll
        for (int j = 0; j < 16; j++) t[j] = sna3b[j];
        const __half2* xr = reinterpret_cast<const __half2*>(g_x2h + (size_t)i * HID);
        for (int k2 = 0; k2 < HID / 2; k2++) {
            float2 f = __half22float2(xr[k2]);
#pragma unroll
            for (int j = 0; j < 16; j++)
                t[j] += f.x * sna3[(k2 * 2) * 16 + j] + f.y * sna3[(k2 * 2 + 1) * 16 + j];
        }
#pragma unroll
        for (int j = 0; j < 16; j++) t[j] = fmaxf(t[j], 0.f);
#pragma unroll
        for (int j = 0; j < 16; j++) {
            float a = sna4b[j];
#pragma unroll
            for (int k = 0; k < 16; k++) a += t[k] * sna4[k * 16 + j];
            xf[32 + j] = fmaxf(a, 0.f);
        }
    }

    // --- fusion head ---
    float h64[64];
#pragma unroll
    for (int j = 0; j < 64; j++) {
        float a = sf1b[j];
#pragma unroll
        for (int k = 0; k < 48; k++) a += xf[k] * sf1[k * 64 + j];
        h64[j] = fmaxf(a, 0.f);
    }
    float h32b[32];
#pragma unroll
    for (int j = 0; j < 32; j++) {
        float a = sf2b[j];
#pragma unroll
        for (int k = 0; k < 64; k++) a += h64[k] * sf2[k * 32 + j];
        h32b[j] = fmaxf(a, 0.f);
    }
    float z = sf3b[0];
#pragma unroll
    for (int k = 0; k < 32; k++) z += h32b[k] * sf3[k];
    out[i] = 1.f / (1.f + expf(-z));
}

// ---------------------------------------------------------------------------
extern "C" void kernel_launch(void* const* d_in, const int* in_sizes, int n_in,
                              void* d_out, int out_size) {
    const float* x        = (const float*)d_in[0];
    const void*  ei       = d_in[1];               // int32 OR int64 — detected on device
    const float* conv1_w  = (const float*)d_in[2];
    const float* conv1_b  = (const float*)d_in[3];
    const float* conv2_w  = (const float*)d_in[4];
    const float* conv2_b  = (const float*)d_in[5];
    const float* ln1_w = (const float*)d_in[6];   const float* ln1_b = (const float*)d_in[7];
    const float* ln2_w = (const float*)d_in[8];   const float* ln2_b = (const float*)d_in[9];
    const float* na1_w = (const float*)d_in[10];  const float* na1_b = (const float*)d_in[11];
    const float* na2_w = (const float*)d_in[12];  const float* na2_b = (const float*)d_in[13];
    const float* na3_w = (const float*)d_in[14];  const float* na3_b = (const float*)d_in[15];
    const float* na4_w = (const float*)d_in[16];  const float* na4_b = (const float*)d_in[17];
    const float* f1_w  = (const float*)d_in[18];  const float* f1_b  = (const float*)d_in[19];
    const float* f2_w  = (const float*)d_in[20];  const float* f2_b  = (const float*)d_in[21];
    const float* f3_w  = (const float*)d_in[22];  const float* f3_b  = (const float*)d_in[23];

    int n = in_sizes[0] / INC;
    int E = in_sizes[1] / 2;        // element count is 2E for either dtype
    if (E > EMAX) E = EMAX;
    if (n > NMAX) n = NMAX;

    int eb = (E + 255) / 256;
    int nb = (n + 255) / 256;

    // ---- CSR build (no edge-list intermediates) ----
    k_init  <<<nb, 256>>>((const int*)ei, E * 2, n, conv2_w);
    k_count <<<eb, 256>>>(ei, E, n);
    k_alloc <<<nb, 256>>>(n);
    k_fill  <<<eb, 256>>>(ei, E, n);

    int gather_blocks = (n * 32 + 255) / 256;

    // ---- conv1 ----
    k_gemm1  <<<(n + 15) / 16, 128>>>(x, conv1_w, n);
    k_gather <<<gather_blocks, 256>>>(conv1_b, n, 0);

    // ---- conv2 (tensor cores) ----
    k_gemm2_mma <<<(n + 63) / 64, 128>>>(n);
    k_gather    <<<gather_blocks, 256>>>(conv2_b, n, 1);

    // ---- heads + fusion ----
    k_mlp<<<(n + 127) / 128, 128>>>(x,
        ln1_w, ln1_b, ln2_w, ln2_b,
        na1_w, na1_b, na2_w, na2_b,
        na3_w, na3_b, na4_w, na4_b,
        f1_w, f1_b, f2_w, f2_b, f3_w, f3_b,
        (float*)d_out, n);
}